// round 15
// baseline (speedup 1.0000x reference)
#include <cuda_runtime.h>
#include <cuda_fp16.h>
#include <cstdint>

#define NN 8192
#define DD 128
#define MAXNB 512
#define STASH 64
#define NEG_SLOPE 0.2f

// ---------------- device scratch (no allocations allowed) ----------------
__device__ __half g_h0[(size_t)NN * DD];   // layer-0 features, fp16
__device__ __half g_h1[(size_t)NN * DD];   // layer-1 features, fp16
__device__ float g_asrc0[NN];
__device__ float g_adst0[NN];
__device__ float g_asrc1[NN];
__device__ float g_adst1[NN];
__device__ int   g_col[(size_t)NN * MAXNB];
__device__ int   g_cnt[NN];

// ---------------- 1) GEMM: h0 = X @ W0 + attention coefficients ------------
// BM=64, BN=128, BK=16, 512 threads, 4x4 outputs/thread, grid=128.
__global__ __launch_bounds__(512) void gemm_xw(const float* __restrict__ X,
                                               const float* __restrict__ W,
                                               const float* __restrict__ att_src,
                                               const float* __restrict__ att_dst,
                                               __half* __restrict__ Hh) {
    __shared__ float As[16][64];
    __shared__ float Bs[16][128];
    const int tid  = threadIdx.x;
    const int lane = tid & 31;
    const int wrp  = tid >> 5;
    const int rowBase = blockIdx.x * 64;

    float acc[4][4];
    #pragma unroll
    for (int i = 0; i < 4; i++)
        #pragma unroll
        for (int j = 0; j < 4; j++) acc[i][j] = 0.0f;

    for (int k0 = 0; k0 < DD; k0 += 16) {
        {
            int r  = tid >> 3;
            int kq = (tid & 7) * 2;
            float2 v = *reinterpret_cast<const float2*>(
                &X[(size_t)(rowBase + r) * DD + k0 + kq]);
            As[kq + 0][r] = v.x;
            As[kq + 1][r] = v.y;
        }
        {
            int kr = tid >> 5;
            int cq = (tid & 31) * 4;
            *reinterpret_cast<float4*>(&Bs[kr][cq]) =
                *reinterpret_cast<const float4*>(&W[(size_t)(k0 + kr) * DD + cq]);
        }
        __syncthreads();
        #pragma unroll
        for (int k = 0; k < 16; k++) {
            float4 a4 = *reinterpret_cast<const float4*>(&As[k][wrp * 4]);
            float4 b4 = *reinterpret_cast<const float4*>(&Bs[k][lane * 4]);
            float a[4] = {a4.x, a4.y, a4.z, a4.w};
            float b[4] = {b4.x, b4.y, b4.z, b4.w};
            #pragma unroll
            for (int i = 0; i < 4; i++)
                #pragma unroll
                for (int j = 0; j < 4; j++)
                    acc[i][j] = fmaf(a[i], b[j], acc[i][j]);
        }
        __syncthreads();
    }

    #pragma unroll
    for (int i = 0; i < 4; i++) {
        __half2 p0 = __float22half2_rn(make_float2(acc[i][0], acc[i][1]));
        __half2 p1 = __float22half2_rn(make_float2(acc[i][2], acc[i][3]));
        uint2 pk;
        pk.x = *reinterpret_cast<unsigned*>(&p0);
        pk.y = *reinterpret_cast<unsigned*>(&p1);
        *reinterpret_cast<uint2*>(&Hh[(size_t)(rowBase + wrp * 4 + i) * DD + lane * 4]) = pk;
    }

    float4 s4 = *reinterpret_cast<const float4*>(&att_src[lane * 4]);
    float4 d4 = *reinterpret_cast<const float4*>(&att_dst[lane * 4]);
    #pragma unroll
    for (int i = 0; i < 4; i++) {
        float ps = acc[i][0] * s4.x + acc[i][1] * s4.y + acc[i][2] * s4.z + acc[i][3] * s4.w;
        float pd = acc[i][0] * d4.x + acc[i][1] * d4.y + acc[i][2] * d4.z + acc[i][3] * d4.w;
        #pragma unroll
        for (int o = 16; o > 0; o >>= 1) {
            ps += __shfl_xor_sync(0xffffffffu, ps, o);
            pd += __shfl_xor_sync(0xffffffffu, pd, o);
        }
        if (lane == 0) {
            g_asrc0[rowBase + wrp * 4 + i] = ps;
            g_adst0[rowBase + wrp * 4 + i] = pd;
        }
    }
}

// ---------------- 2) fused scan + layer-0 agg, micro-batched ---------------
// Warp-per-row. Per 512-col macro-chunk: 4 independent stream loads (MLP 4),
// ballot-compact nonzeros into a per-warp smem stash, drain stash 4-deep
// (gathers at MLP 4), copy stash to g_col. Epilogue: out0, W1 matvec, attn1.
__global__ __launch_bounds__(512) void fused_scan_agg0(const float* __restrict__ adj,
                                                       const float* __restrict__ bias,
                                                       float* __restrict__ out0,
                                                       const float* __restrict__ W1,
                                                       const float* __restrict__ att_src1,
                                                       const float* __restrict__ att_dst1) {
    const int w    = threadIdx.x >> 5;
    const int lane = threadIdx.x & 31;
    const int i    = blockIdx.x * 16 + w;

    __shared__ float xs[16][DD];
    __shared__ int   stash[16][STASH];

    const float4* __restrict__ row4 = reinterpret_cast<const float4*>(adj + (size_t)i * NN);
    const uint2* __restrict__ H0u  = reinterpret_cast<const uint2*>(g_h0);  // 32 per row
    int* __restrict__ col = g_col + (size_t)i * MAXNB;
    const float adst_i = g_adst0[i];
    const unsigned ltmask = (1u << lane) - 1u;

    float acc0 = 0.f, acc1 = 0.f, acc2 = 0.f, acc3 = 0.f;  // channels lane*4..+3
    float sum = 0.0f;
    int cnt = 0;

    #define COMPACT(vv, base) do {                                             \
        unsigned m0 = __ballot_sync(0xffffffffu, (vv).x != 0.0f);              \
        unsigned m1 = __ballot_sync(0xffffffffu, (vv).y != 0.0f);              \
        unsigned m2 = __ballot_sync(0xffffffffu, (vv).z != 0.0f);              \
        unsigned m3 = __ballot_sync(0xffffffffu, (vv).w != 0.0f);              \
        int b = (base) + lane * 4;                                             \
        if ((vv).x != 0.0f) { int p = nloc + __popc(m0 & ltmask); if (p < STASH) stash[w][p] = b; } \
        nloc += __popc(m0);                                                    \
        if ((vv).y != 0.0f) { int p = nloc + __popc(m1 & ltmask); if (p < STASH) stash[w][p] = b + 1; } \
        nloc += __popc(m1);                                                    \
        if ((vv).z != 0.0f) { int p = nloc + __popc(m2 & ltmask); if (p < STASH) stash[w][p] = b + 2; } \
        nloc += __popc(m2);                                                    \
        if ((vv).w != 0.0f) { int p = nloc + __popc(m3 & ltmask); if (p < STASH) stash[w][p] = b + 3; } \
        nloc += __popc(m3);                                                    \
    } while (0)

    for (int mc = 0; mc < NN; mc += 512) {
        const int fb = mc >> 2;              // float4 base index
        float4 v0 = row4[fb + lane];
        float4 v1 = row4[fb + 32 + lane];
        float4 v2 = row4[fb + 64 + lane];
        float4 v3 = row4[fb + 96 + lane];

        int nloc = 0;
        COMPACT(v0, mc);
        COMPACT(v1, mc + 128);
        COMPACT(v2, mc + 256);
        COMPACT(v3, mc + 384);
        nloc = nloc < STASH ? nloc : STASH;
        __syncwarp();

        // copy stash to the layer-1 neighbor list (few entries)
        for (int t = lane; t < nloc; t += 32) {
            int p = cnt + t;
            if (p < MAXNB) col[p] = stash[w][t];
        }
        cnt += nloc;

        // drain stash: 4-deep unrolled gather+softmax accumulation
        for (int k = 0; k < nloc; k += 4) {
            int j0 = stash[w][k];
            int j1 = (k + 1 < nloc) ? stash[w][k + 1] : 0;
            int j2 = (k + 2 < nloc) ? stash[w][k + 2] : 0;
            int j3 = (k + 3 < nloc) ? stash[w][k + 3] : 0;
            float e0 = g_asrc0[j0] + adst_i;
            float e1 = g_asrc0[j1] + adst_i;
            float e2 = g_asrc0[j2] + adst_i;
            float e3 = g_asrc0[j3] + adst_i;
            e0 = e0 >= 0.f ? e0 : NEG_SLOPE * e0;
            e1 = e1 >= 0.f ? e1 : NEG_SLOPE * e1;
            e2 = e2 >= 0.f ? e2 : NEG_SLOPE * e2;
            e3 = e3 >= 0.f ? e3 : NEG_SLOPE * e3;
            float w0 = __expf(e0);
            float w1 = (k + 1 < nloc) ? __expf(e1) : 0.f;
            float w2 = (k + 2 < nloc) ? __expf(e2) : 0.f;
            float w3 = (k + 3 < nloc) ? __expf(e3) : 0.f;
            uint2 u0 = H0u[(size_t)j0 * 32 + lane];
            uint2 u1 = H0u[(size_t)j1 * 32 + lane];
            uint2 u2 = H0u[(size_t)j2 * 32 + lane];
            uint2 u3 = H0u[(size_t)j3 * 32 + lane];
            sum += (w0 + w1) + (w2 + w3);
            #define ACC4(wv, u) do {                                           \
                __half2 q0 = *reinterpret_cast<const __half2*>(&(u).x);        \
                __half2 q1 = *reinterpret_cast<const __half2*>(&(u).y);        \
                float2 f0 = __half22float2(q0);                                \
                float2 f1 = __half22float2(q1);                                \
                acc0 = fmaf((wv), f0.x, acc0); acc1 = fmaf((wv), f0.y, acc1);  \
                acc2 = fmaf((wv), f1.x, acc2); acc3 = fmaf((wv), f1.y, acc3);  \
            } while (0)
            ACC4(w0, u0); ACC4(w1, u1); ACC4(w2, u2); ACC4(w3, u3);
            #undef ACC4
        }
        __syncwarp();   // stash reuse barrier
    }
    #undef COMPACT

    if (lane == 0) g_cnt[i] = cnt < MAXNB ? cnt : MAXNB;

    // epilogue: bias + relu, store out0, stash row for matvec
    const float inv = 1.0f / sum;
    float4 b4 = *reinterpret_cast<const float4*>(&bias[lane * 4]);
    float4 o4;
    o4.x = fmaxf(fmaf(acc0, inv, b4.x), 0.0f);
    o4.y = fmaxf(fmaf(acc1, inv, b4.y), 0.0f);
    o4.z = fmaxf(fmaf(acc2, inv, b4.z), 0.0f);
    o4.w = fmaxf(fmaf(acc3, inv, b4.w), 0.0f);
    reinterpret_cast<float4*>(out0)[(size_t)i * 32 + lane] = o4;
    *reinterpret_cast<float4*>(&xs[w][lane * 4]) = o4;
    __syncwarp();

    // matvec: h1[c] = sum_k xs[k] * W1[k][c]; lane owns c = lane*4..+3
    const float4* __restrict__ W14 = reinterpret_cast<const float4*>(W1);
    float4 m = make_float4(0.f, 0.f, 0.f, 0.f);
    #pragma unroll 4
    for (int k = 0; k < DD; k++) {
        float xk = xs[w][k];
        float4 wv = W14[k * 32 + lane];
        m.x = fmaf(xk, wv.x, m.x);
        m.y = fmaf(xk, wv.y, m.y);
        m.z = fmaf(xk, wv.z, m.z);
        m.w = fmaf(xk, wv.w, m.w);
    }
    {
        __half2 p0 = __float22half2_rn(make_float2(m.x, m.y));
        __half2 p1 = __float22half2_rn(make_float2(m.z, m.w));
        uint2 pk;
        pk.x = *reinterpret_cast<unsigned*>(&p0);
        pk.y = *reinterpret_cast<unsigned*>(&p1);
        *reinterpret_cast<uint2*>(&g_h1[(size_t)i * DD + lane * 4]) = pk;
    }

    // layer-1 attention coefficients: warp reduce
    float4 s4 = *reinterpret_cast<const float4*>(&att_src1[lane * 4]);
    float4 d4 = *reinterpret_cast<const float4*>(&att_dst1[lane * 4]);
    float ps = m.x * s4.x + m.y * s4.y + m.z * s4.z + m.w * s4.w;
    float pd = m.x * d4.x + m.y * d4.y + m.z * d4.z + m.w * d4.w;
    #pragma unroll
    for (int o = 16; o > 0; o >>= 1) {
        ps += __shfl_xor_sync(0xffffffffu, ps, o);
        pd += __shfl_xor_sync(0xffffffffu, pd, o);
    }
    if (lane == 0) {
        g_asrc1[i] = ps;
        g_adst1[i] = pd;
    }
}

// ---------------- 3) layer-1 softmax + aggregation -------------------------
// Block-per-row, 128 threads; max-free softmax, uint4 gathers.
__global__ __launch_bounds__(128) void aggregate1(const __half* __restrict__ Hh,
                                                  const float* __restrict__ bias,
                                                  float* __restrict__ out) {
    const int i    = blockIdx.x;
    const int tid  = threadIdx.x;
    const int lane = tid & 31;
    const int w    = tid >> 5;
    const int half = lane >> 4;
    const int pos  = lane & 15;
    __shared__ float se[MAXNB + 16];
    __shared__ int   sc[MAXNB + 16];
    __shared__ float reds[4];
    __shared__ float accs[4][DD];

    const int cnt = g_cnt[i];
    const float adst_i = g_adst1[i];
    const int* __restrict__ col = g_col + (size_t)i * MAXNB;

    float lsum = 0.0f;
    for (int k = tid; k < cnt; k += 128) {
        int j = col[k];
        sc[k] = j;
        float e = g_asrc1[j] + adst_i;
        e = e >= 0.0f ? e : NEG_SLOPE * e;
        float wv = __expf(e);
        se[k] = wv;
        lsum += wv;
    }
    if (tid < 16) { se[cnt + tid] = 0.0f; sc[cnt + tid] = 0; }
    #pragma unroll
    for (int o = 16; o > 0; o >>= 1)
        lsum += __shfl_xor_sync(0xffffffffu, lsum, o);
    if (lane == 0) reds[w] = lsum;
    __syncthreads();
    const float inv = 1.0f / (reds[0] + reds[1] + reds[2] + reds[3]);

    const uint4* __restrict__ H4 = reinterpret_cast<const uint4*>(Hh);
    float acc[8];
    #pragma unroll
    for (int c = 0; c < 8; c++) acc[c] = 0.0f;

    #define ACC8(wv, u) do {                                              \
        __half2 q0 = *reinterpret_cast<const __half2*>(&(u).x);           \
        __half2 q1 = *reinterpret_cast<const __half2*>(&(u).y);           \
        __half2 q2 = *reinterpret_cast<const __half2*>(&(u).z);           \
        __half2 q3 = *reinterpret_cast<const __half2*>(&(u).w);           \
        float2 f0 = __half22float2(q0); float2 f1 = __half22float2(q1);   \
        float2 f2 = __half22float2(q2); float2 f3 = __half22float2(q3);   \
        acc[0] = fmaf((wv), f0.x, acc[0]); acc[1] = fmaf((wv), f0.y, acc[1]); \
        acc[2] = fmaf((wv), f1.x, acc[2]); acc[3] = fmaf((wv), f1.y, acc[3]); \
        acc[4] = fmaf((wv), f2.x, acc[4]); acc[5] = fmaf((wv), f2.y, acc[5]); \
        acc[6] = fmaf((wv), f3.x, acc[6]); acc[7] = fmaf((wv), f3.y, acc[7]); \
    } while (0)

    for (int k = w * 2 + half; k < cnt; k += 16) {
        float w0 = se[k];
        float w1 = se[k + 8];
        int   j0 = sc[k];
        int   j1 = sc[k + 8];
        uint4 u0 = H4[(size_t)j0 * 16 + pos];
        uint4 u1 = H4[(size_t)j1 * 16 + pos];
        ACC8(w0, u0);
        ACC8(w1, u1);
    }
    #undef ACC8

    #pragma unroll
    for (int c = 0; c < 8; c++)
        acc[c] += __shfl_xor_sync(0xffffffffu, acc[c], 16);

    if (half == 0) {
        *reinterpret_cast<float4*>(&accs[w][pos * 8]) =
            make_float4(acc[0], acc[1], acc[2], acc[3]);
        *reinterpret_cast<float4*>(&accs[w][pos * 8 + 4]) =
            make_float4(acc[4], acc[5], acc[6], acc[7]);
    }
    __syncthreads();

    float s = accs[0][tid] + accs[1][tid] + accs[2][tid] + accs[3][tid];
    out[(size_t)i * DD + tid] = fmaf(s, inv, bias[tid]);
}

// ---------------- launch ---------------------------------------------------
extern "C" void kernel_launch(void* const* d_in, const int* in_sizes, int n_in,
                              void* d_out, int out_size) {
    const float* x        = (const float*)d_in[0];
    const float* adj      = (const float*)d_in[1];
    const float* W0       = (const float*)d_in[2];
    const float* att_src0 = (const float*)d_in[3];
    const float* att_dst0 = (const float*)d_in[4];
    const float* b0       = (const float*)d_in[5];
    const float* W1       = (const float*)d_in[6];
    const float* att_src1 = (const float*)d_in[7];
    const float* att_dst1 = (const float*)d_in[8];
    const float* b1       = (const float*)d_in[9];

    float* out0 = (float*)d_out;
    float* out1 = (float*)d_out + (size_t)NN * DD;

    __half *h0, *h1;
    cudaGetSymbolAddress((void**)&h0, g_h0);
    cudaGetSymbolAddress((void**)&h1, g_h1);

    // 1) layer-0 feature transform (needs no adj)
    gemm_xw<<<NN / 64, 512>>>(x, W0, att_src0, att_dst0, h0);
    // 2) single pass over adj: micro-batched list build + layer-0 aggregation
    //    + layer-1 matvec
    fused_scan_agg0<<<NN / 16, 512>>>(adj, b0, out0, W1, att_src1, att_dst1);
    // 3) layer-1 aggregation over the cached lists
    aggregate1<<<NN, 128>>>(h1, b1, out1);
}

// round 16
// speedup vs baseline: 1.2481x; 1.2481x over previous
#include <cuda_runtime.h>
#include <cuda_fp16.h>
#include <cstdint>

#define NN 8192
#define DD 128
#define MAXNB 512
#define NEG_SLOPE 0.2f

#define BUILD_BLOCKS 512     // 512-thread blocks, 16 rows each
#define GEMM_BLOCKS  128     // BM=64

// ---------------- device scratch (no allocations allowed) ----------------
__device__ __half g_hh[(size_t)NN * DD];   // transformed features, fp16
__device__ float g_asrc[NN];
__device__ float g_adst[NN];
__device__ int   g_col[(size_t)NN * MAXNB];
__device__ int   g_cnt[NN];

// ---------------- adjacency scan body --------------------------------------
__device__ __forceinline__ void build_row(const float* __restrict__ adj, int row_id, int lane) {
    const float4* row = reinterpret_cast<const float4*>(adj + (size_t)row_id * NN);
    int* col = g_col + (size_t)row_id * MAXNB;
    const unsigned ltmask = (1u << lane) - 1u;
    int cnt = 0;
    #pragma unroll 4
    for (int j0 = 0; j0 < NN; j0 += 128) {
        float4 v = row[(j0 >> 2) + lane];
        int base = j0 + lane * 4;
        unsigned m0 = __ballot_sync(0xffffffffu, v.x != 0.0f);
        unsigned m1 = __ballot_sync(0xffffffffu, v.y != 0.0f);
        unsigned m2 = __ballot_sync(0xffffffffu, v.z != 0.0f);
        unsigned m3 = __ballot_sync(0xffffffffu, v.w != 0.0f);
        if (v.x != 0.0f) { int p = cnt + __popc(m0 & ltmask); if (p < MAXNB) col[p] = base + 0; }
        cnt += __popc(m0);
        if (v.y != 0.0f) { int p = cnt + __popc(m1 & ltmask); if (p < MAXNB) col[p] = base + 1; }
        cnt += __popc(m1);
        if (v.z != 0.0f) { int p = cnt + __popc(m2 & ltmask); if (p < MAXNB) col[p] = base + 2; }
        cnt += __popc(m2);
        if (v.w != 0.0f) { int p = cnt + __popc(m3 & ltmask); if (p < MAXNB) col[p] = base + 3; }
        cnt += __popc(m3);
    }
    if (lane == 0) g_cnt[row_id] = cnt < MAXNB ? cnt : MAXNB;
}

// ---------------- GEMM body (BM=64, 512 thr, 4x4/thread) -------------------
__device__ __forceinline__ void gemm_tile(const float* __restrict__ X,
                                          const float* __restrict__ W,
                                          const float* __restrict__ att_src,
                                          const float* __restrict__ att_dst,
                                          __half* __restrict__ Hh,
                                          int rowBase) {
    __shared__ float As[16][64];
    __shared__ float Bs[16][128];
    const int tid  = threadIdx.x;
    const int lane = tid & 31;
    const int wrp  = tid >> 5;

    float acc[4][4];
    #pragma unroll
    for (int i = 0; i < 4; i++)
        #pragma unroll
        for (int j = 0; j < 4; j++) acc[i][j] = 0.0f;

    for (int k0 = 0; k0 < DD; k0 += 16) {
        {
            int r  = tid >> 3;
            int kq = (tid & 7) * 2;
            float2 v = *reinterpret_cast<const float2*>(
                &X[(size_t)(rowBase + r) * DD + k0 + kq]);
            As[kq + 0][r] = v.x;
            As[kq + 1][r] = v.y;
        }
        {
            int kr = tid >> 5;
            int cq = (tid & 31) * 4;
            *reinterpret_cast<float4*>(&Bs[kr][cq]) =
                *reinterpret_cast<const float4*>(&W[(size_t)(k0 + kr) * DD + cq]);
        }
        __syncthreads();
        #pragma unroll
        for (int k = 0; k < 16; k++) {
            float4 a4 = *reinterpret_cast<const float4*>(&As[k][wrp * 4]);
            float4 b4 = *reinterpret_cast<const float4*>(&Bs[k][lane * 4]);
            float a[4] = {a4.x, a4.y, a4.z, a4.w};
            float b[4] = {b4.x, b4.y, b4.z, b4.w};
            #pragma unroll
            for (int i = 0; i < 4; i++)
                #pragma unroll
                for (int j = 0; j < 4; j++)
                    acc[i][j] = fmaf(a[i], b[j], acc[i][j]);
        }
        __syncthreads();
    }

    #pragma unroll
    for (int i = 0; i < 4; i++) {
        __half2 p0 = __float22half2_rn(make_float2(acc[i][0], acc[i][1]));
        __half2 p1 = __float22half2_rn(make_float2(acc[i][2], acc[i][3]));
        uint2 pk;
        pk.x = *reinterpret_cast<unsigned*>(&p0);
        pk.y = *reinterpret_cast<unsigned*>(&p1);
        *reinterpret_cast<uint2*>(&Hh[(size_t)(rowBase + wrp * 4 + i) * DD + lane * 4]) = pk;
    }

    float4 s4 = *reinterpret_cast<const float4*>(&att_src[lane * 4]);
    float4 d4 = *reinterpret_cast<const float4*>(&att_dst[lane * 4]);
    #pragma unroll
    for (int i = 0; i < 4; i++) {
        float ps = acc[i][0] * s4.x + acc[i][1] * s4.y + acc[i][2] * s4.z + acc[i][3] * s4.w;
        float pd = acc[i][0] * d4.x + acc[i][1] * d4.y + acc[i][2] * d4.z + acc[i][3] * d4.w;
        #pragma unroll
        for (int o = 16; o > 0; o >>= 1) {
            ps += __shfl_xor_sync(0xffffffffu, ps, o);
            pd += __shfl_xor_sync(0xffffffffu, pd, o);
        }
        if (lane == 0) {
            g_asrc[rowBase + wrp * 4 + i] = ps;
            g_adst[rowBase + wrp * 4 + i] = pd;
        }
    }
}

// ---------------- fused: adjacency scan (grid head) + layer-0 GEMM ---------
__global__ __launch_bounds__(512) void fused_build_gemm(const float* __restrict__ adj,
                                                        const float* __restrict__ X,
                                                        const float* __restrict__ W,
                                                        const float* __restrict__ att_src,
                                                        const float* __restrict__ att_dst,
                                                        __half* __restrict__ Hh) {
    if (blockIdx.x < BUILD_BLOCKS) {
        int row_id = (blockIdx.x * 512 + threadIdx.x) >> 5;
        build_row(adj, row_id, threadIdx.x & 31);
    } else {
        gemm_tile(X, W, att_src, att_dst, Hh, (blockIdx.x - BUILD_BLOCKS) * 64);
    }
}

__global__ __launch_bounds__(512) void gemm_xw(const float* __restrict__ X,
                                               const float* __restrict__ W,
                                               const float* __restrict__ att_src,
                                               const float* __restrict__ att_dst,
                                               __half* __restrict__ Hh) {
    gemm_tile(X, W, att_src, att_dst, Hh, blockIdx.x * 64);
}

// ---------------- softmax + sparse aggregation -----------------------------
// Block-per-row, 128 threads. Max-free softmax; (weight,index) packed as one
// float2 smem entry (single LDS.64 per neighbor access). Phase C: uint4
// gathers, 16 lanes per row, 2 neighbors per warp-round, shfl_xor(16) merge.
__global__ __launch_bounds__(128) void aggregate(const __half* __restrict__ Hh,
                                                 const float* __restrict__ bias,
                                                 float* __restrict__ out,
                                                 int do_relu) {
    const int i    = blockIdx.x;
    const int tid  = threadIdx.x;
    const int lane = tid & 31;
    const int w    = tid >> 5;
    const int half = lane >> 4;
    const int pos  = lane & 15;
    __shared__ float2 swj[MAXNB + 16];     // (.x = exp weight, .y = index bits)
    __shared__ float reds[4];
    __shared__ float accs[4][DD];

    const int cnt = g_cnt[i];
    const float adst_i = g_adst[i];
    const int* __restrict__ col = g_col + (size_t)i * MAXNB;

    // fused logits -> leaky relu -> exp -> block sum; pack (w, j) together
    float lsum = 0.0f;
    for (int k = tid; k < cnt; k += 128) {
        int j = col[k];
        float e = g_asrc[j] + adst_i;
        e = e >= 0.0f ? e : NEG_SLOPE * e;
        float wv = __expf(e);
        swj[k] = make_float2(wv, __int_as_float(j));
        lsum += wv;
    }
    if (tid < 16) swj[cnt + tid] = make_float2(0.0f, __int_as_float(0));
    #pragma unroll
    for (int o = 16; o > 0; o >>= 1)
        lsum += __shfl_xor_sync(0xffffffffu, lsum, o);
    if (lane == 0) reds[w] = lsum;
    __syncthreads();
    const float inv = 1.0f / (reds[0] + reds[1] + reds[2] + reds[3]);

    // phase C: each lane accumulates 8 channels (one uint4 = 8 fp16)
    const uint4* __restrict__ H4 = reinterpret_cast<const uint4*>(Hh);  // 16 per row
    float acc[8];
    #pragma unroll
    for (int c = 0; c < 8; c++) acc[c] = 0.0f;

    #define ACC8(wv, u) do {                                              \
        __half2 q0 = *reinterpret_cast<const __half2*>(&(u).x);           \
        __half2 q1 = *reinterpret_cast<const __half2*>(&(u).y);           \
        __half2 q2 = *reinterpret_cast<const __half2*>(&(u).z);           \
        __half2 q3 = *reinterpret_cast<const __half2*>(&(u).w);           \
        float2 f0 = __half22float2(q0); float2 f1 = __half22float2(q1);   \
        float2 f2 = __half22float2(q2); float2 f3 = __half22float2(q3);   \
        acc[0] = fmaf((wv), f0.x, acc[0]); acc[1] = fmaf((wv), f0.y, acc[1]); \
        acc[2] = fmaf((wv), f1.x, acc[2]); acc[3] = fmaf((wv), f1.y, acc[3]); \
        acc[4] = fmaf((wv), f2.x, acc[4]); acc[5] = fmaf((wv), f2.y, acc[5]); \
        acc[6] = fmaf((wv), f3.x, acc[6]); acc[7] = fmaf((wv), f3.y, acc[7]); \
    } while (0)

    // warp w, lane-half h covers k = w*2 + h + 8t; 2-deep unroll (k, k+8).
    for (int k = w * 2 + half; k < cnt; k += 16) {
        float2 p0 = swj[k];
        float2 p1 = swj[k + 8];
        int   j0 = __float_as_int(p0.y);
        int   j1 = __float_as_int(p1.y);
        uint4 u0 = H4[(size_t)j0 * 16 + pos];
        uint4 u1 = H4[(size_t)j1 * 16 + pos];
        ACC8(p0.x, u0);
        ACC8(p1.x, u1);
    }
    #undef ACC8

    // combine the two lane-halves; lanes 0-15 then hold channel sums
    #pragma unroll
    for (int c = 0; c < 8; c++)
        acc[c] += __shfl_xor_sync(0xffffffffu, acc[c], 16);

    if (half == 0) {
        *reinterpret_cast<float4*>(&accs[w][pos * 8]) =
            make_float4(acc[0], acc[1], acc[2], acc[3]);
        *reinterpret_cast<float4*>(&accs[w][pos * 8 + 4]) =
            make_float4(acc[4], acc[5], acc[6], acc[7]);
    }
    __syncthreads();

    float s = accs[0][tid] + accs[1][tid] + accs[2][tid] + accs[3][tid];
    float o = fmaf(s, inv, bias[tid]);
    if (do_relu) o = fmaxf(o, 0.0f);
    out[(size_t)i * DD + tid] = o;
}

// ---------------- launch ---------------------------------------------------
extern "C" void kernel_launch(void* const* d_in, const int* in_sizes, int n_in,
                              void* d_out, int out_size) {
    const float* x        = (const float*)d_in[0];
    const float* adj      = (const float*)d_in[1];
    const float* W0       = (const float*)d_in[2];
    const float* att_src0 = (const float*)d_in[3];
    const float* att_dst0 = (const float*)d_in[4];
    const float* b0       = (const float*)d_in[5];
    const float* W1       = (const float*)d_in[6];
    const float* att_src1 = (const float*)d_in[7];
    const float* att_dst1 = (const float*)d_in[8];
    const float* b1       = (const float*)d_in[9];

    float* out0 = (float*)d_out;
    float* out1 = (float*)d_out + (size_t)NN * DD;

    __half* hh;
    cudaGetSymbolAddress((void**)&hh, g_hh);

    // build (grid head) + layer-0 GEMM (grid tail) overlap in one launch
    fused_build_gemm<<<BUILD_BLOCKS + GEMM_BLOCKS, 512>>>(adj, x, W0, att_src0, att_dst0, hh);
    aggregate<<<NN, 128>>>(hh, b0, out0, 1);

    gemm_xw<<<GEMM_BLOCKS, 512>>>(out0, W1, att_src1, att_dst1, hh);
    aggregate<<<NN, 128>>>(hh, b1, out1, 0);
}